// round 3
// baseline (speedup 1.0000x reference)
#include <cuda_runtime.h>
#include <cuda_bf16.h>
#include <math.h>

#define NTOK 2048
#define CDIM 1024
#define NHEADS 8
#define HD 128
#define NGROUPS 32
#define SPATIAL 64
#define EPS 1e-5f

// ---------------- device scratch (no allocation allowed) ----------------
__device__ float g_feat[NTOK * CDIM];        // 8 MB
__device__ float g_featn[NTOK * CDIM];       // 8 MB
__device__ float g_qkv[NTOK * 3 * CDIM];     // 24 MB
__device__ float g_attnout[NTOK * CDIM];     // 8 MB
__device__ float g_proj[NTOK * CDIM];        // 8 MB
__device__ int   g_gidx[NTOK];
__device__ int   g_counts[NGROUPS];
__device__ int   g_offs[NGROUPS];
__device__ int   g_sidx[NTOK];

// ---------------- 1. batch_indices: dtype-detect + convert + histogram ----------------
__global__ void k_gidx(const void* __restrict__ bi_raw) {
    __shared__ int is64;
    __shared__ int hc[NGROUPS];
    const int tid = threadIdx.x;
    const int* w32 = (const int*)bi_raw;
    if (tid == 0) {
        // int64 data with values in [0,32): every odd (high) 32-bit word is 0.
        // For int32 data those words are batch indices; P(all 32 are 0) ~ 32^-32.
        int odd_nonzero = 0;
        for (int i = 1; i < 64; i += 2) odd_nonzero |= (w32[i] != 0);
        is64 = !odd_nonzero;
    }
    if (tid < NGROUPS) hc[tid] = 0;
    __syncthreads();
    if (is64) {
        const long long* p = (const long long*)bi_raw;
        for (int i = tid; i < NTOK; i += blockDim.x) g_gidx[i] = (int)p[i];
    } else {
        for (int i = tid; i < NTOK; i += blockDim.x) g_gidx[i] = w32[i];
    }
    __syncthreads();
    for (int i = tid; i < NTOK; i += blockDim.x) atomicAdd(&hc[g_gidx[i]], 1);
    __syncthreads();
    if (tid == 0) {
        int o = 0;
        for (int g = 0; g < NGROUPS; g++) {
            g_offs[g] = o;
            g_counts[g] = hc[g];
            o += hc[g];
        }
    }
}

// ---------------- 2. deterministic stable scatter (rank = # earlier same-group tokens) ----
__global__ void k_rank() {
    int n = blockIdx.x * blockDim.x + threadIdx.x;
    if (n >= NTOK) return;
    int g = g_gidx[n];
    int r = 0;
    for (int m = 0; m < n; m++) r += (g_gidx[m] == g);
    g_sidx[g_offs[g] + r] = n;
}

// ---------------- 3. spatial mean pool: one warp per (n,c) row of 64 ----------------
__global__ void k_feat(const float* __restrict__ x) {
    int w = (blockIdx.x * blockDim.x + threadIdx.x) >> 5;
    int lane = threadIdx.x & 31;
    if (w >= NTOK * CDIM) return;
    const float* p = x + (size_t)w * SPATIAL;
    float s = p[lane] + p[lane + 32];
    #pragma unroll
    for (int o = 16; o > 0; o >>= 1) s += __shfl_xor_sync(0xffffffffu, s, o);
    if (lane == 0) g_feat[w] = s * (1.0f / 64.0f);
}

// ---------------- 4. layernorm over C per token ----------------
__global__ void k_ln(const float* __restrict__ lnw, const float* __restrict__ lnb) {
    int n = blockIdx.x;
    int tid = threadIdx.x;           // 256 threads, 4 elems each
    const float* row = g_feat + (size_t)n * CDIM;
    float4 v = *(const float4*)(row + tid * 4);
    float s = v.x + v.y + v.z + v.w;
    float q = v.x * v.x + v.y * v.y + v.z * v.z + v.w * v.w;
    __shared__ float ssum[8], ssq[8];
    #pragma unroll
    for (int o = 16; o > 0; o >>= 1) {
        s += __shfl_xor_sync(0xffffffffu, s, o);
        q += __shfl_xor_sync(0xffffffffu, q, o);
    }
    int lane = tid & 31, wp = tid >> 5;
    if (lane == 0) { ssum[wp] = s; ssq[wp] = q; }
    __syncthreads();
    __shared__ float mu_s, rstd_s;
    if (tid == 0) {
        float S = 0.f, Q = 0.f;
        for (int i = 0; i < 8; i++) { S += ssum[i]; Q += ssq[i]; }
        float mu = S * (1.0f / CDIM);
        float var = Q * (1.0f / CDIM) - mu * mu;
        mu_s = mu;
        rstd_s = rsqrtf(var + EPS);
    }
    __syncthreads();
    float mu = mu_s, rstd = rstd_s;
    float4 wv = *(const float4*)(lnw + tid * 4);
    float4 bv = *(const float4*)(lnb + tid * 4);
    float4 o;
    o.x = (v.x - mu) * rstd * wv.x + bv.x;
    o.y = (v.y - mu) * rstd * wv.y + bv.y;
    o.z = (v.z - mu) * rstd * wv.z + bv.z;
    o.w = (v.w - mu) * rstd * wv.w + bv.w;
    *(float4*)(g_featn + (size_t)n * CDIM + tid * 4) = o;
}

// ---------------- 5. SGEMM: C[M,N] = A[M,K] * B[N,K]^T + bias[N] ----------------
// BM=BN=128, BK=16, 256 threads, 8x8 micro-tile.
#define BM 128
#define BN 128
#define BK 16
__global__ void __launch_bounds__(256)
k_sgemm_nt(const float* __restrict__ A, const float* __restrict__ B,
           const float* __restrict__ bias, float* __restrict__ C,
           int M, int N, int K) {
    __shared__ float As[BK][BM];
    __shared__ float Bs[BK][BN];
    const int t = threadIdx.x;
    const int trow = (t >> 4) * 8;
    const int tcol = (t & 15) * 8;
    const float* Ab = A + (size_t)blockIdx.y * BM * K;
    const float* Bb = B + (size_t)blockIdx.x * BN * K;
    float acc[8][8];
    #pragma unroll
    for (int i = 0; i < 8; i++)
        #pragma unroll
        for (int j = 0; j < 8; j++) acc[i][j] = 0.f;

    for (int k0 = 0; k0 < K; k0 += BK) {
        #pragma unroll
        for (int l = 0; l < 2; l++) {
            int f = t + l * 256;          // float4 slot (0..511)
            int row = f >> 2;             // tile row 0..127
            int c4 = (f & 3) * 4;         // k offset 0,4,8,12
            float4 av = *(const float4*)(Ab + (size_t)row * K + k0 + c4);
            As[c4 + 0][row] = av.x; As[c4 + 1][row] = av.y;
            As[c4 + 2][row] = av.z; As[c4 + 3][row] = av.w;
            float4 bv = *(const float4*)(Bb + (size_t)row * K + k0 + c4);
            Bs[c4 + 0][row] = bv.x; Bs[c4 + 1][row] = bv.y;
            Bs[c4 + 2][row] = bv.z; Bs[c4 + 3][row] = bv.w;
        }
        __syncthreads();
        #pragma unroll
        for (int kk = 0; kk < BK; kk++) {
            float a[8], b[8];
            *(float4*)(a)     = *(const float4*)&As[kk][trow];
            *(float4*)(a + 4) = *(const float4*)&As[kk][trow + 4];
            *(float4*)(b)     = *(const float4*)&Bs[kk][tcol];
            *(float4*)(b + 4) = *(const float4*)&Bs[kk][tcol + 4];
            #pragma unroll
            for (int i = 0; i < 8; i++)
                #pragma unroll
                for (int j = 0; j < 8; j++) acc[i][j] = fmaf(a[i], b[j], acc[i][j]);
        }
        __syncthreads();
    }
    #pragma unroll
    for (int i = 0; i < 8; i++) {
        size_t m = (size_t)blockIdx.y * BM + trow + i;
        #pragma unroll
        for (int j = 0; j < 8; j += 4) {
            int n = blockIdx.x * BN + tcol + j;
            float4 o;
            o.x = acc[i][j + 0] + bias[n + 0];
            o.y = acc[i][j + 1] + bias[n + 1];
            o.z = acc[i][j + 2] + bias[n + 2];
            o.w = acc[i][j + 3] + bias[n + 3];
            *(float4*)(C + m * N + n) = o;
        }
    }
}

// ---------------- 6. per-group flash attention ----------------
// grid: (NGROUPS, NHEADS); block: 256 (8 warps). Each warp streams 8 queries.
__global__ void __launch_bounds__(256)
k_attn() {
    const int g = blockIdx.x;
    const int h = blockIdx.y;
    const int n = g_counts[g];
    if (n == 0) return;
    const int base = g_offs[g];
    const int warp = threadIdx.x >> 5;
    const int lane = threadIdx.x & 31;
    __shared__ float Ks[32][HD];
    __shared__ float Vs[32][HD];
    const float scale = 0.08838834764831843f;  // 1/sqrt(128)

    for (int q0 = 0; q0 < n; q0 += 64) {
        float qreg[8][4], m[8], l[8], acc[8][4];
        #pragma unroll
        for (int qi = 0; qi < 8; qi++) {
            m[qi] = -INFINITY; l[qi] = 0.f;
            acc[qi][0] = acc[qi][1] = acc[qi][2] = acc[qi][3] = 0.f;
            int qidx = q0 + warp * 8 + qi;
            if (qidx < n) {
                int tk = g_sidx[base + qidx];
                float4 qv = *(const float4*)(g_qkv + (size_t)tk * 3072 + h * HD + lane * 4);
                qreg[qi][0] = qv.x; qreg[qi][1] = qv.y;
                qreg[qi][2] = qv.z; qreg[qi][3] = qv.w;
            } else {
                qreg[qi][0] = qreg[qi][1] = qreg[qi][2] = qreg[qi][3] = 0.f;
            }
        }
        for (int k0 = 0; k0 < n; k0 += 32) {
            const int tn = min(32, n - k0);
            __syncthreads();
            for (int i = threadIdx.x; i < tn * 32; i += 256) {  // float4 units
                int tok = i >> 5;
                int d4 = (i & 31) * 4;
                int tk = g_sidx[base + k0 + tok];
                *(float4*)&Ks[tok][d4] =
                    *(const float4*)(g_qkv + (size_t)tk * 3072 + CDIM + h * HD + d4);
                *(float4*)&Vs[tok][d4] =
                    *(const float4*)(g_qkv + (size_t)tk * 3072 + 2 * CDIM + h * HD + d4);
            }
            __syncthreads();
            for (int j = 0; j < tn; j++) {
                float4 kv = *(const float4*)&Ks[j][lane * 4];
                float4 vv = *(const float4*)&Vs[j][lane * 4];
                #pragma unroll
                for (int qi = 0; qi < 8; qi++) {
                    float s = qreg[qi][0] * kv.x + qreg[qi][1] * kv.y +
                              qreg[qi][2] * kv.z + qreg[qi][3] * kv.w;
                    #pragma unroll
                    for (int o = 16; o > 0; o >>= 1)
                        s += __shfl_xor_sync(0xffffffffu, s, o);
                    s *= scale;
                    float mn = fmaxf(m[qi], s);
                    float cc = __expf(m[qi] - mn);   // exp(-inf)=0 first iter
                    float p = __expf(s - mn);
                    m[qi] = mn;
                    l[qi] = l[qi] * cc + p;
                    acc[qi][0] = acc[qi][0] * cc + p * vv.x;
                    acc[qi][1] = acc[qi][1] * cc + p * vv.y;
                    acc[qi][2] = acc[qi][2] * cc + p * vv.z;
                    acc[qi][3] = acc[qi][3] * cc + p * vv.w;
                }
            }
        }
        #pragma unroll
        for (int qi = 0; qi < 8; qi++) {
            int qidx = q0 + warp * 8 + qi;
            if (qidx < n) {
                int tk = g_sidx[base + qidx];
                float inv = 1.0f / l[qi];
                float4 o;
                o.x = acc[qi][0] * inv; o.y = acc[qi][1] * inv;
                o.z = acc[qi][2] * inv; o.w = acc[qi][3] * inv;
                *(float4*)(g_attnout + (size_t)tk * CDIM + h * HD + lane * 4) = o;
            }
        }
    }
}

// ---------------- 7. residual add with gating ----------------
__global__ void k_final(const float* __restrict__ x, const float* __restrict__ gamma,
                        float* __restrict__ y) {
    size_t i = (size_t)blockIdx.x * blockDim.x + threadIdx.x;  // float4 index
    size_t total4 = (size_t)NTOK * CDIM * SPATIAL / 4;
    if (i >= total4) return;
    size_t e = i * 4;
    int nc = (int)(e >> 6);        // (n,c) flat index
    int n = nc >> 10;
    float d = 0.f;
    if (g_counts[g_gidx[n]] > 1) d = gamma[0] * g_proj[nc];
    float4 xv = *(const float4*)(x + e);
    xv.x += d; xv.y += d; xv.z += d; xv.w += d;
    *(float4*)(y + e) = xv;
}

// ---------------- launch ----------------
extern "C" void kernel_launch(void* const* d_in, const int* in_sizes, int n_in,
                              void* d_out, int out_size) {
    const float* x        = (const float*)d_in[0];
    const void*  bidx     = d_in[1];
    const float* ln_w     = (const float*)d_in[2];
    const float* ln_b     = (const float*)d_in[3];
    const float* inp_w    = (const float*)d_in[4];
    const float* inp_b    = (const float*)d_in[5];
    const float* outp_w   = (const float*)d_in[6];
    const float* outp_b   = (const float*)d_in[7];
    const float* gamma    = (const float*)d_in[8];
    float* y = (float*)d_out;

    float *featn, *qkv, *attnout, *proj;
    cudaGetSymbolAddress((void**)&featn, g_featn);
    cudaGetSymbolAddress((void**)&qkv, g_qkv);
    cudaGetSymbolAddress((void**)&attnout, g_attnout);
    cudaGetSymbolAddress((void**)&proj, g_proj);

    k_gidx<<<1, 256>>>(bidx);
    k_rank<<<NTOK / 256, 256>>>();
    k_feat<<<(NTOK * CDIM * 32) / 256, 256>>>(x);
    k_ln<<<NTOK, 256>>>(ln_w, ln_b);
    k_sgemm_nt<<<dim3(3 * CDIM / BN, NTOK / BM), 256>>>(featn, inp_w, inp_b, qkv,
                                                        NTOK, 3 * CDIM, CDIM);
    k_attn<<<dim3(NGROUPS, NHEADS), 256>>>();
    k_sgemm_nt<<<dim3(CDIM / BN, NTOK / BM), 256>>>(attnout, outp_w, outp_b, proj,
                                                    NTOK, CDIM, CDIM);
    size_t total4 = (size_t)NTOK * CDIM * SPATIAL / 4;
    k_final<<<(unsigned)((total4 + 255) / 256), 256>>>(x, gamma, y);
}

// round 6
// speedup vs baseline: 1.5460x; 1.5460x over previous
#include <cuda_runtime.h>
#include <cuda_bf16.h>
#include <math.h>
#include <cstdint>

#define NTOK 2048
#define CDIM 1024
#define NHEADS 8
#define HD 128
#define NGROUPS 32
#define SPATIAL 64
#define EPS 1e-5f

// ---------------- device scratch (no allocation allowed) ----------------
__device__ float g_feat[NTOK * CDIM];        // 8 MB
__device__ float g_featn[NTOK * CDIM];       // 8 MB
__device__ float g_qkv[NTOK * 3 * CDIM];     // 24 MB
__device__ float g_attnout[NTOK * CDIM];     // 8 MB
__device__ float g_proj[NTOK * CDIM];        // 8 MB
__device__ int   g_gidx[NTOK];
__device__ int   g_counts[NGROUPS];
__device__ int   g_offs[NGROUPS];
__device__ int   g_sidx[NTOK];

__device__ __forceinline__ uint32_t smem_u32(const void* p) {
    uint32_t a;
    asm("{ .reg .u64 t; cvta.to.shared.u64 t, %1; cvt.u32.u64 %0, t; }" : "=r"(a) : "l"(p));
    return a;
}

// ---------------- 1. batch_indices: dtype-detect + convert + histogram ----------------
__global__ void k_gidx(const void* __restrict__ bi_raw) {
    __shared__ int is64;
    __shared__ int hc[NGROUPS];
    const int tid = threadIdx.x;
    const int* w32 = (const int*)bi_raw;
    if (tid == 0) {
        int odd_nonzero = 0;
        for (int i = 1; i < 64; i += 2) odd_nonzero |= (w32[i] != 0);
        is64 = !odd_nonzero;
    }
    if (tid < NGROUPS) hc[tid] = 0;
    __syncthreads();
    if (is64) {
        const long long* p = (const long long*)bi_raw;
        for (int i = tid; i < NTOK; i += blockDim.x) g_gidx[i] = (int)p[i];
    } else {
        for (int i = tid; i < NTOK; i += blockDim.x) g_gidx[i] = w32[i];
    }
    __syncthreads();
    for (int i = tid; i < NTOK; i += blockDim.x) atomicAdd(&hc[g_gidx[i]], 1);
    __syncthreads();
    if (tid == 0) {
        int o = 0;
        for (int g = 0; g < NGROUPS; g++) {
            g_offs[g] = o;
            g_counts[g] = hc[g];
            o += hc[g];
        }
    }
}

// ---------------- 2. deterministic stable scatter ----------------
__global__ void __launch_bounds__(1024) k_rank() {
    __shared__ int sg[NTOK];
    for (int i = threadIdx.x; i < NTOK; i += 1024) sg[i] = g_gidx[i];
    __syncthreads();
    for (int n = threadIdx.x; n < NTOK; n += 1024) {
        int g = sg[n];
        int r = 0;
        for (int m = 0; m < NTOK; m++) r += (m < n) & (sg[m] == g);
        g_sidx[g_offs[g] + r] = n;
    }
}

// ---------------- 3. spatial mean pool ----------------
__global__ void k_feat(const float* __restrict__ x) {
    int w = (blockIdx.x * blockDim.x + threadIdx.x) >> 5;
    int lane = threadIdx.x & 31;
    if (w >= NTOK * CDIM) return;
    const float* p = x + (size_t)w * SPATIAL;
    float s = p[lane] + p[lane + 32];
    #pragma unroll
    for (int o = 16; o > 0; o >>= 1) s += __shfl_xor_sync(0xffffffffu, s, o);
    if (lane == 0) g_feat[w] = s * (1.0f / 64.0f);
}

// ---------------- 4. layernorm over C per token ----------------
__global__ void k_ln(const float* __restrict__ lnw, const float* __restrict__ lnb) {
    int n = blockIdx.x;
    int tid = threadIdx.x;
    const float* row = g_feat + (size_t)n * CDIM;
    float4 v = *(const float4*)(row + tid * 4);
    float s = v.x + v.y + v.z + v.w;
    float q = v.x * v.x + v.y * v.y + v.z * v.z + v.w * v.w;
    __shared__ float ssum[8], ssq[8];
    #pragma unroll
    for (int o = 16; o > 0; o >>= 1) {
        s += __shfl_xor_sync(0xffffffffu, s, o);
        q += __shfl_xor_sync(0xffffffffu, q, o);
    }
    int lane = tid & 31, wp = tid >> 5;
    if (lane == 0) { ssum[wp] = s; ssq[wp] = q; }
    __syncthreads();
    __shared__ float mu_s, rstd_s;
    if (tid == 0) {
        float S = 0.f, Q = 0.f;
        for (int i = 0; i < 8; i++) { S += ssum[i]; Q += ssq[i]; }
        float mu = S * (1.0f / CDIM);
        float var = Q * (1.0f / CDIM) - mu * mu;
        mu_s = mu;
        rstd_s = rsqrtf(var + EPS);
    }
    __syncthreads();
    float mu = mu_s, rstd = rstd_s;
    float4 wv = *(const float4*)(lnw + tid * 4);
    float4 bv = *(const float4*)(lnb + tid * 4);
    float4 o;
    o.x = (v.x - mu) * rstd * wv.x + bv.x;
    o.y = (v.y - mu) * rstd * wv.y + bv.y;
    o.z = (v.z - mu) * rstd * wv.z + bv.z;
    o.w = (v.w - mu) * rstd * wv.w + bv.w;
    *(float4*)(g_featn + (size_t)n * CDIM + tid * 4) = o;
}

// ---------------- 5. tf32 mma.sync GEMM: C[M,N] = A[M,K]*B[N,K]^T + bias ----------------
// CTA 128x128, K-chunk 32, cp.async double buffer. 8 warps in 2(m)x4(n); warp tile 64x32.
// Smem rows padded to 36 floats: frag addr 36g+tg -> bank (4g+tg)%32, conflict-free.
#define GKC 32
#define RS 36
#define GEMM_SMEM (4 * 128 * RS * 4)   // 2 bufs x (A+B) x 128 rows x 36 floats

#define MMA_TF32(c, a, b)                                                     \
    asm volatile("mma.sync.aligned.m16n8k8.row.col.f32.tf32.tf32.f32 "        \
        "{%0,%1,%2,%3}, {%4,%5,%6,%7}, {%8,%9}, {%0,%1,%2,%3};"               \
        : "+f"((c)[0]), "+f"((c)[1]), "+f"((c)[2]), "+f"((c)[3])              \
        : "r"((a)[0]), "r"((a)[1]), "r"((a)[2]), "r"((a)[3]),                 \
          "r"((b)[0]), "r"((b)[1]))

__global__ void __launch_bounds__(256)
k_gemm_mma(const float* __restrict__ A, const float* __restrict__ B,
           const float* __restrict__ bias, float* __restrict__ C, int N, int K) {
    extern __shared__ float sm[];
    float* As = sm;                      // [2][128*RS]
    float* Bs = sm + 2 * 128 * RS;       // [2][128*RS]

    const int t = threadIdx.x;
    const int wid = t >> 5, lane = t & 31;
    const int wm = wid >> 2;             // 0..1  (64-row slab)
    const int wn = wid & 3;              // 0..3  (32-col slab)
    const int g = lane >> 2, tg = lane & 3;

    const float* Ab = A + (size_t)blockIdx.y * 128 * K;
    const float* Bb = B + (size_t)blockIdx.x * 128 * K;

    float acc[4][4][4];
    #pragma unroll
    for (int i = 0; i < 4; i++)
        #pragma unroll
        for (int j = 0; j < 4; j++)
            #pragma unroll
            for (int k = 0; k < 4; k++) acc[i][j][k] = 0.f;

    const int nch = K / GKC;

    // ---- async chunk loader ----
    auto load_chunk = [&](int ch) {
        const int buf = ch & 1;
        const int k0 = ch * GKC;
        float* Ad = As + buf * 128 * RS;
        float* Bd = Bs + buf * 128 * RS;
        #pragma unroll
        for (int l = 0; l < 4; l++) {
            int f = t + l * 256;
            int row = f >> 3;            // 0..127
            int c8 = f & 7;              // 16B unit within 128B row
            uint32_t da = smem_u32(Ad + row * RS + c8 * 4);
            const float* sa = Ab + (size_t)row * K + k0 + c8 * 4;
            asm volatile("cp.async.ca.shared.global [%0], [%1], 16;" :: "r"(da), "l"(sa));
            uint32_t db = smem_u32(Bd + row * RS + c8 * 4);
            const float* sb = Bb + (size_t)row * K + k0 + c8 * 4;
            asm volatile("cp.async.ca.shared.global [%0], [%1], 16;" :: "r"(db), "l"(sb));
        }
        asm volatile("cp.async.commit_group;" ::: "memory");
    };

    load_chunk(0);
    for (int ch = 0; ch < nch; ch++) {
        if (ch + 1 < nch) {
            load_chunk(ch + 1);
            asm volatile("cp.async.wait_group 1;" ::: "memory");
        } else {
            asm volatile("cp.async.wait_group 0;" ::: "memory");
        }
        __syncthreads();

        const int buf = ch & 1;
        const float* Ad = As + buf * 128 * RS + (wm * 64) * RS;
        const float* Bd = Bs + buf * 128 * RS + (wn * 32) * RS;
        #pragma unroll
        for (int kk = 0; kk < 4; kk++) {
            uint32_t af[4][4], bf[4][2];
            #pragma unroll
            for (int mt = 0; mt < 4; mt++) {
                const float* p = Ad + (mt * 16 + g) * RS + kk * 8 + tg;
                af[mt][0] = __float_as_uint(p[0]);
                af[mt][1] = __float_as_uint(p[8 * RS]);
                af[mt][2] = __float_as_uint(p[4]);
                af[mt][3] = __float_as_uint(p[8 * RS + 4]);
            }
            #pragma unroll
            for (int nt = 0; nt < 4; nt++) {
                const float* p = Bd + (nt * 8 + g) * RS + kk * 8 + tg;
                bf[nt][0] = __float_as_uint(p[0]);
                bf[nt][1] = __float_as_uint(p[4]);
            }
            #pragma unroll
            for (int mt = 0; mt < 4; mt++)
                #pragma unroll
                for (int nt = 0; nt < 4; nt++)
                    MMA_TF32(acc[mt][nt], af[mt], bf[nt]);
        }
        __syncthreads();
    }

    // ---- epilogue: direct float2 stores + bias ----
    const int mbase = blockIdx.y * 128 + wm * 64;
    const int nbase = blockIdx.x * 128 + wn * 32;
    #pragma unroll
    for (int mt = 0; mt < 4; mt++) {
        #pragma unroll
        for (int nt = 0; nt < 4; nt++) {
            int row = mbase + mt * 16 + g;
            int col = nbase + nt * 8 + tg * 2;
            float2 bi = *(const float2*)(bias + col);
            float2 v0 = make_float2(acc[mt][nt][0] + bi.x, acc[mt][nt][1] + bi.y);
            float2 v1 = make_float2(acc[mt][nt][2] + bi.x, acc[mt][nt][3] + bi.y);
            *(float2*)(C + (size_t)row * N + col) = v0;
            *(float2*)(C + (size_t)(row + 8) * N + col) = v1;
        }
    }
}

// ---------------- 6. per-group flash attention ----------------
__global__ void __launch_bounds__(256)
k_attn() {
    const int g = blockIdx.x;
    const int h = blockIdx.y;
    const int n = g_counts[g];
    if (n == 0) return;
    const int base = g_offs[g];
    const int warp = threadIdx.x >> 5;
    const int lane = threadIdx.x & 31;
    __shared__ float Ks[32][HD];
    __shared__ float Vs[32][HD];
    const float scale = 0.08838834764831843f;  // 1/sqrt(128)

    for (int q0 = 0; q0 < n; q0 += 64) {
        float qreg[8][4], m[8], l[8], acc[8][4];
        #pragma unroll
        for (int qi = 0; qi < 8; qi++) {
            m[qi] = -INFINITY; l[qi] = 0.f;
            acc[qi][0] = acc[qi][1] = acc[qi][2] = acc[qi][3] = 0.f;
            int qidx = q0 + warp * 8 + qi;
            if (qidx < n) {
                int tk = g_sidx[base + qidx];
                float4 qv = *(const float4*)(g_qkv + (size_t)tk * 3072 + h * HD + lane * 4);
                qreg[qi][0] = qv.x; qreg[qi][1] = qv.y;
                qreg[qi][2] = qv.z; qreg[qi][3] = qv.w;
            } else {
                qreg[qi][0] = qreg[qi][1] = qreg[qi][2] = qreg[qi][3] = 0.f;
            }
        }
        for (int k0 = 0; k0 < n; k0 += 32) {
            const int tn = min(32, n - k0);
            __syncthreads();
            for (int i = threadIdx.x; i < tn * 32; i += 256) {
                int tok = i >> 5;
                int d4 = (i & 31) * 4;
                int tk = g_sidx[base + k0 + tok];
                *(float4*)&Ks[tok][d4] =
                    *(const float4*)(g_qkv + (size_t)tk * 3072 + CDIM + h * HD + d4);
                *(float4*)&Vs[tok][d4] =
                    *(const float4*)(g_qkv + (size_t)tk * 3072 + 2 * CDIM + h * HD + d4);
            }
            __syncthreads();
            for (int j = 0; j < tn; j++) {
                float4 kv = *(const float4*)&Ks[j][lane * 4];
                float4 vv = *(const float4*)&Vs[j][lane * 4];
                #pragma unroll
                for (int qi = 0; qi < 8; qi++) {
                    float s = qreg[qi][0] * kv.x + qreg[qi][1] * kv.y +
                              qreg[qi][2] * kv.z + qreg[qi][3] * kv.w;
                    #pragma unroll
                    for (int o = 16; o > 0; o >>= 1)
                        s += __shfl_xor_sync(0xffffffffu, s, o);
                    s *= scale;
                    float mn = fmaxf(m[qi], s);
                    float cc = __expf(m[qi] - mn);
                    float p = __expf(s - mn);
                    m[qi] = mn;
                    l[qi] = l[qi] * cc + p;
                    acc[qi][0] = acc[qi][0] * cc + p * vv.x;
                    acc[qi][1] = acc[qi][1] * cc + p * vv.y;
                    acc[qi][2] = acc[qi][2] * cc + p * vv.z;
                    acc[qi][3] = acc[qi][3] * cc + p * vv.w;
                }
            }
        }
        #pragma unroll
        for (int qi = 0; qi < 8; qi++) {
            int qidx = q0 + warp * 8 + qi;
            if (qidx < n) {
                int tk = g_sidx[base + qidx];
                float inv = 1.0f / l[qi];
                float4 o;
                o.x = acc[qi][0] * inv; o.y = acc[qi][1] * inv;
                o.z = acc[qi][2] * inv; o.w = acc[qi][3] * inv;
                *(float4*)(g_attnout + (size_t)tk * CDIM + h * HD + lane * 4) = o;
            }
        }
    }
}

// ---------------- 7. residual add with gating ----------------
__global__ void k_final(const float* __restrict__ x, const float* __restrict__ gamma,
                        float* __restrict__ y) {
    size_t i = (size_t)blockIdx.x * blockDim.x + threadIdx.x;
    size_t total4 = (size_t)NTOK * CDIM * SPATIAL / 4;
    if (i >= total4) return;
    size_t e = i * 4;
    int nc = (int)(e >> 6);
    int n = nc >> 10;
    float d = 0.f;
    if (g_counts[g_gidx[n]] > 1) d = gamma[0] * g_proj[nc];
    float4 xv = *(const float4*)(x + e);
    xv.x += d; xv.y += d; xv.z += d; xv.w += d;
    *(float4*)(y + e) = xv;
}

// ---------------- launch ----------------
extern "C" void kernel_launch(void* const* d_in, const int* in_sizes, int n_in,
                              void* d_out, int out_size) {
    const float* x        = (const float*)d_in[0];
    const void*  bidx     = d_in[1];
    const float* ln_w     = (const float*)d_in[2];
    const float* ln_b     = (const float*)d_in[3];
    const float* inp_w    = (const float*)d_in[4];
    const float* inp_b    = (const float*)d_in[5];
    const float* outp_w   = (const float*)d_in[6];
    const float* outp_b   = (const float*)d_in[7];
    const float* gamma    = (const float*)d_in[8];
    float* y = (float*)d_out;

    float *featn, *qkv, *attnout, *proj;
    cudaGetSymbolAddress((void**)&featn, g_featn);
    cudaGetSymbolAddress((void**)&qkv, g_qkv);
    cudaGetSymbolAddress((void**)&attnout, g_attnout);
    cudaGetSymbolAddress((void**)&proj, g_proj);

    cudaFuncSetAttribute(k_gemm_mma, cudaFuncAttributeMaxDynamicSharedMemorySize,
                         GEMM_SMEM);

    k_gidx<<<1, 256>>>(bidx);
    k_rank<<<1, 1024>>>();
    k_feat<<<(NTOK * CDIM * 32) / 256, 256>>>(x);
    k_ln<<<NTOK, 256>>>(ln_w, ln_b);
    k_gemm_mma<<<dim3(3 * CDIM / 128, NTOK / 128), 256, GEMM_SMEM>>>(
        featn, inp_w, inp_b, qkv, 3 * CDIM, CDIM);
    k_attn<<<dim3(NGROUPS, NHEADS), 256>>>();
    k_gemm_mma<<<dim3(CDIM / 128, NTOK / 128), 256, GEMM_SMEM>>>(
        attnout, outp_w, outp_b, proj, CDIM, CDIM);
    size_t total4 = (size_t)NTOK * CDIM * SPATIAL / 4;
    k_final<<<(unsigned)((total4 + 255) / 256), 256>>>(x, gamma, y);
}